// round 1
// baseline (speedup 1.0000x reference)
#include <cuda_runtime.h>

#define NN 50000
#define NE 800000
#define H 128
#define ED 32
#define BN_EPS 1e-5f
#define RES_SCALE 0.1f

// ---------------- scratch (device globals; allocation-free) ----------------
__device__ __align__(16) float g_h[NN * H];
__device__ __align__(16) float g_z[NN * H];
__device__ __align__(16) float g_t[NN * H];
__device__ __align__(16) float g_z2[NN * H];
__device__ int g_src[NE];
__device__ int g_dstv[NE];
__device__ int g_eid[NE];
__device__ int g_cnt[NN];
__device__ int g_rowptr[NN + 1];
__device__ int g_cursor[NN];
__device__ __align__(16) float g_colsum[H];
__device__ __align__(16) float g_colsq[H];
__device__ __align__(16) float g_scale[H];
__device__ __align__(16) float g_shift[H];
__device__ int g_i64;

// ---------------- init: h = x, zero counts ----------------
__global__ void k_init(const float* __restrict__ x) {
    int i = blockIdx.x * blockDim.x + threadIdx.x;
    if (i < NN * H) g_h[i] = x[i];
    if (i < NN) g_cnt[i] = 0;
}

// Detect whether edge_index buffer is int64 or int32 (little-endian: int64
// values < 2^31 have zero high words at odd int32 positions).
__global__ void k_detect(const int* __restrict__ p) {
    if (threadIdx.x == 0 && blockIdx.x == 0) {
        int all_hi_zero = 1;
        for (int k = 0; k < 64; k++) {
            if (p[2 * k + 1] != 0) { all_hi_zero = 0; break; }
        }
        g_i64 = all_hi_zero;
    }
}

// ---------------- CSR build ----------------
__global__ void k_prep(const int* __restrict__ p) {
    int e = blockIdx.x * blockDim.x + threadIdx.x;
    if (e >= NE) return;
    int s, d;
    if (g_i64) {
        const long long* q = (const long long*)p;
        s = (int)q[e];
        d = (int)q[NE + e];
    } else {
        s = p[e];
        d = p[NE + e];
    }
    g_src[e] = s;
    g_dstv[e] = d;
    atomicAdd(&g_cnt[d], 1);
}

__global__ void k_scan() {
    __shared__ int sd[1024];
    __shared__ int sbase;
    int tid = threadIdx.x;
    if (tid == 0) sbase = 0;
    __syncthreads();
    for (int start = 0; start < NN; start += 1024) {
        int i = start + tid;
        int v = (i < NN) ? g_cnt[i] : 0;
        sd[tid] = v;
        __syncthreads();
        for (int off = 1; off < 1024; off <<= 1) {
            int t = (tid >= off) ? sd[tid - off] : 0;
            __syncthreads();
            sd[tid] += t;
            __syncthreads();
        }
        int excl = sd[tid] - v;
        if (i < NN) {
            g_rowptr[i] = sbase + excl;
            g_cursor[i] = sbase + excl;
        }
        int tot = sd[1023];
        __syncthreads();
        if (tid == 0) sbase += tot;
        __syncthreads();
    }
    if (tid == 0) g_rowptr[NN] = sbase;
}

__global__ void k_scatter() {
    int e = blockIdx.x * blockDim.x + threadIdx.x;
    if (e >= NE) return;
    int pos = atomicAdd(&g_cursor[g_dstv[e]], 1);
    g_eid[pos] = e;
}

// ---------------- edge message + segment sum: z = h + sum relu(h[src]+ea@We+be)
// one warp per node; lane handles cols 4*lane..4*lane+3
__global__ void k_agg(const float* __restrict__ ea, const float* __restrict__ We,
                      const float* __restrict__ be) {
    __shared__ float sWe[ED * H];
    __shared__ float sbe[H];
    int tid = threadIdx.x;
    for (int i = tid; i < ED * H; i += 256) sWe[i] = We[i];
    if (tid < H) sbe[tid] = be[tid];
    __syncthreads();
    int lane = tid & 31;
    int node = blockIdx.x * 8 + (tid >> 5);
    if (node >= NN) return;
    int beg = g_rowptr[node];
    int end = g_rowptr[node + 1];
    float4 acc = *(const float4*)(g_h + (size_t)node * H + lane * 4);
    float4 bias = *(const float4*)(sbe + lane * 4);
    for (int j = beg; j < end; j++) {
        int e = g_eid[j];
        int s = g_src[e];
        float eav = ea[(size_t)e * ED + lane];
        float4 m = bias;
#pragma unroll
        for (int k = 0; k < ED; k++) {
            float a = __shfl_sync(0xffffffffu, eav, k);
            float4 w = *(const float4*)(sWe + k * H + lane * 4);
            m.x += a * w.x;
            m.y += a * w.y;
            m.z += a * w.z;
            m.w += a * w.w;
        }
        float4 hv = *(const float4*)(g_h + (size_t)s * H + lane * 4);
        acc.x += fmaxf(m.x + hv.x, 0.f);
        acc.y += fmaxf(m.y + hv.y, 0.f);
        acc.z += fmaxf(m.z + hv.z, 0.f);
        acc.w += fmaxf(m.w + hv.w, 0.f);
    }
    *(float4*)(g_z + (size_t)node * H + lane * 4) = acc;
}

// ---------------- tiled GEMM: C[N,128] = A[N,128] @ W[128,128] + b (opt relu)
// which==0: A=g_z, C=g_t, relu.  which==1: A=g_t, C=g_z2, no relu.
__global__ void k_gemm(int which, const float* __restrict__ W,
                       const float* __restrict__ bias) {
    const float* A = (which == 0) ? g_z : g_t;
    float* C = (which == 0) ? g_t : g_z2;
    bool relu = (which == 0);
    __shared__ float As[64 * 32];
    __shared__ float Ws[32 * 128];
    int tid = threadIdx.x;
    int tx = tid & 31;
    int ty = tid >> 5;
    int row0 = blockIdx.x * 64;
    float acc[8][4];
#pragma unroll
    for (int j = 0; j < 8; j++) {
        acc[j][0] = 0.f; acc[j][1] = 0.f; acc[j][2] = 0.f; acc[j][3] = 0.f;
    }
    for (int kt = 0; kt < 4; kt++) {
        for (int i = tid; i < 512; i += 256) {
            int r = i >> 3;
            int c4 = i & 7;
            int gr = row0 + r;
            float4 v = make_float4(0.f, 0.f, 0.f, 0.f);
            if (gr < NN) v = *(const float4*)(A + (size_t)gr * H + kt * 32 + c4 * 4);
            *(float4*)(As + r * 32 + c4 * 4) = v;
        }
        for (int i = tid; i < 1024; i += 256) {
            int k = i >> 5;
            int c4 = i & 31;
            *(float4*)(Ws + k * 128 + c4 * 4) =
                *(const float4*)(W + (size_t)(kt * 32 + k) * H + c4 * 4);
        }
        __syncthreads();
#pragma unroll
        for (int k = 0; k < 32; k++) {
            float4 w = *(const float4*)(Ws + k * 128 + tx * 4);
#pragma unroll
            for (int j = 0; j < 8; j++) {
                float a = As[(ty * 8 + j) * 32 + k];
                acc[j][0] += a * w.x;
                acc[j][1] += a * w.y;
                acc[j][2] += a * w.z;
                acc[j][3] += a * w.w;
            }
        }
        __syncthreads();
    }
    float4 b = *(const float4*)(bias + tx * 4);
#pragma unroll
    for (int j = 0; j < 8; j++) {
        int gr = row0 + ty * 8 + j;
        if (gr < NN) {
            float4 o;
            o.x = acc[j][0] + b.x;
            o.y = acc[j][1] + b.y;
            o.z = acc[j][2] + b.z;
            o.w = acc[j][3] + b.w;
            if (relu) {
                o.x = fmaxf(o.x, 0.f);
                o.y = fmaxf(o.y, 0.f);
                o.z = fmaxf(o.z, 0.f);
                o.w = fmaxf(o.w, 0.f);
            }
            *(float4*)(C + (size_t)gr * H + tx * 4) = o;
        }
    }
}

// ---------------- batchnorm stats ----------------
__global__ void k_zstat() {
    int c = threadIdx.x;
    g_colsum[c] = 0.f;
    g_colsq[c] = 0.f;
}

__global__ void k_bnstats() {
    int c = threadIdx.x;  // 128 threads
    int r0 = blockIdx.x * 256;
    int r1 = r0 + 256;
    if (r1 > NN) r1 = NN;
    float s = 0.f, q = 0.f;
    for (int r = r0; r < r1; r++) {
        float v = g_z2[(size_t)r * H + c];
        s += v;
        q += v * v;
    }
    atomicAdd(&g_colsum[c], s);
    atomicAdd(&g_colsq[c], q);
}

__global__ void k_bnfin(const float* __restrict__ gamma,
                        const float* __restrict__ beta) {
    int c = threadIdx.x;
    float mu = g_colsum[c] * (1.f / NN);
    float var = g_colsq[c] * (1.f / NN) - mu * mu;
    float rs = rsqrtf(var + BN_EPS);
    float sc = rs * gamma[c];
    g_scale[c] = sc;
    g_shift[c] = beta[c] - mu * sc;
}

// ---------------- BN apply + relu + residual ----------------
__global__ void k_post(float* __restrict__ dout, int use_dout) {
    int i = blockIdx.x * blockDim.x + threadIdx.x;
    if (i >= NN * H / 4) return;
    int c4 = i & 31;
    float4 z = ((const float4*)g_z2)[i];
    float4 sc = ((const float4*)g_scale)[c4];
    float4 sh = ((const float4*)g_shift)[c4];
    float4 hr = ((const float4*)g_h)[i];
    float4 o;
    o.x = fmaxf(fmaf(z.x, sc.x, sh.x), 0.f) + RES_SCALE * hr.x;
    o.y = fmaxf(fmaf(z.y, sc.y, sh.y), 0.f) + RES_SCALE * hr.y;
    o.z = fmaxf(fmaf(z.z, sc.z, sh.z), 0.f) + RES_SCALE * hr.z;
    o.w = fmaxf(fmaf(z.w, sc.w, sh.w), 0.f) + RES_SCALE * hr.w;
    float4* out = use_dout ? (float4*)dout : (float4*)g_h;
    out[i] = o;
}

// ---------------- launch ----------------
extern "C" void kernel_launch(void* const* d_in, const int* in_sizes, int n_in,
                              void* d_out, int out_size) {
    const float* x = (const float*)d_in[0];
    const int* ei = (const int*)d_in[1];  // raw; int32 vs int64 detected on device
    const float* ea = (const float*)d_in[2];
    const float* We = (const float*)d_in[3];
    const float* be = (const float*)d_in[4];
    const float* W1 = (const float*)d_in[5];
    const float* b1 = (const float*)d_in[6];
    const float* W2 = (const float*)d_in[7];
    const float* b2 = (const float*)d_in[8];
    const float* gamma = (const float*)d_in[9];
    const float* beta = (const float*)d_in[10];

    k_init<<<(NN * H + 255) / 256, 256>>>(x);
    k_detect<<<1, 32>>>(ei);
    k_prep<<<(NE + 255) / 256, 256>>>(ei);
    k_scan<<<1, 1024>>>();
    k_scatter<<<(NE + 255) / 256, 256>>>();

    for (int l = 0; l < 3; l++) {
        k_agg<<<(NN + 7) / 8, 256>>>(ea, We + (size_t)l * ED * H, be + (size_t)l * H);
        k_gemm<<<(NN + 63) / 64, 256>>>(0, W1 + (size_t)l * H * H, b1 + (size_t)l * H);
        k_gemm<<<(NN + 63) / 64, 256>>>(1, W2 + (size_t)l * H * H, b2 + (size_t)l * H);
        k_zstat<<<1, 128>>>();
        k_bnstats<<<(NN + 255) / 256, 128>>>();
        k_bnfin<<<1, 128>>>(gamma + (size_t)l * H, beta + (size_t)l * H);
        k_post<<<(NN * H / 4 + 255) / 256, 256>>>((float*)d_out, l == 2 ? 1 : 0);
    }
}

// round 2
// speedup vs baseline: 1.6683x; 1.6683x over previous
#include <cuda_runtime.h>

#define NN 50000
#define NE 800000
#define H 128
#define ED 32
#define BN_EPS 1e-5f
#define RES_SCALE 0.1f

// ---------------- scratch (device globals; allocation-free) ----------------
__device__ __align__(16) float g_h[NN * H];
__device__ __align__(16) float g_z[NN * H];
__device__ __align__(16) float g_t[NN * H];
__device__ __align__(16) float g_z2[NN * H];
__device__ int g_src[NE];
__device__ int g_dstv[NE];
__device__ int g_eid[NE];
__device__ int g_ssort[NE];
__device__ int g_cnt[NN];
__device__ int g_rowptr[NN + 1];
__device__ int g_cursor[NN];
__device__ __align__(16) float g_colsum[H];
__device__ __align__(16) float g_colsq[H];
__device__ __align__(16) float g_scale[H];
__device__ __align__(16) float g_shift[H];
__device__ int g_i64;

// ---------------- init: h = x, zero counts ----------------
__global__ void k_init(const float* __restrict__ x) {
    int i = blockIdx.x * blockDim.x + threadIdx.x;
    if (i < NN * H) g_h[i] = x[i];
    if (i < NN) g_cnt[i] = 0;
}

// Detect int64 vs int32 edge_index (little-endian int64 < 2^31 => zero hi words)
__global__ void k_detect(const int* __restrict__ p) {
    if (threadIdx.x == 0 && blockIdx.x == 0) {
        int all_hi_zero = 1;
        for (int k = 0; k < 64; k++) {
            if (p[2 * k + 1] != 0) { all_hi_zero = 0; break; }
        }
        g_i64 = all_hi_zero;
    }
}

// ---------------- CSR build ----------------
__global__ void k_prep(const int* __restrict__ p) {
    int e = blockIdx.x * blockDim.x + threadIdx.x;
    if (e >= NE) return;
    int s, d;
    if (g_i64) {
        const long long* q = (const long long*)p;
        s = (int)q[e];
        d = (int)q[NE + e];
    } else {
        s = p[e];
        d = p[NE + e];
    }
    g_src[e] = s;
    g_dstv[e] = d;
    atomicAdd(&g_cnt[d], 1);
}

// chunked single-block scan: each thread owns CH contiguous elements
__global__ void k_scan() {
    __shared__ int warpsum[32];
    const int CH = (NN + 1023) / 1024;  // 49
    int tid = threadIdx.x;
    int lane = tid & 31, wid = tid >> 5;
    int base = tid * CH;
    int s = 0;
    for (int i = 0; i < CH; i++) {
        int idx = base + i;
        if (idx < NN) s += g_cnt[idx];
    }
    int v = s;
#pragma unroll
    for (int o = 1; o < 32; o <<= 1) {
        int t = __shfl_up_sync(0xffffffffu, v, o);
        if (lane >= o) v += t;
    }
    if (lane == 31) warpsum[wid] = v;
    __syncthreads();
    if (wid == 0) {
        int w = warpsum[lane];
#pragma unroll
        for (int o = 1; o < 32; o <<= 1) {
            int t = __shfl_up_sync(0xffffffffu, w, o);
            if (lane >= o) w += t;
        }
        warpsum[lane] = w;
    }
    __syncthreads();
    int excl = v - s + (wid > 0 ? warpsum[wid - 1] : 0);
    int run = excl;
    for (int i = 0; i < CH; i++) {
        int idx = base + i;
        if (idx < NN) {
            g_rowptr[idx] = run;
            g_cursor[idx] = run;
            run += g_cnt[idx];
        }
    }
    if (tid == 1023) g_rowptr[NN] = run;
}

__global__ void k_scatter() {
    int e = blockIdx.x * blockDim.x + threadIdx.x;
    if (e >= NE) return;
    int d = g_dstv[e];
    int pos = atomicAdd(&g_cursor[d], 1);
    g_eid[pos] = e;
    g_ssort[pos] = g_src[e];
}

// ---------------- edge message + segment sum ----------------
// z = h + sum_{e->node} relu(h[src] + ea@We + be)
// 2 warps per node; each warp owns 64 cols; weights live in registers.
__global__ void __launch_bounds__(256) k_agg(const float* __restrict__ ea,
                                             const float* __restrict__ We,
                                             const float* __restrict__ be) {
    int tid = threadIdx.x;
    int lane = tid & 31;
    int w = tid >> 5;                  // 0..7
    int node = blockIdx.x * 4 + (w >> 1);
    int half = w & 1;
    int c0 = half * 64 + lane * 2;

    // per-lane weight slice: We[k][c0..c0+1], k=0..31  (64 regs)
    float2 wreg[ED];
#pragma unroll
    for (int k = 0; k < ED; k++)
        wreg[k] = *(const float2*)(We + (size_t)k * H + c0);

    if (node >= NN) return;
    float2 bias = *(const float2*)(be + c0);
    float2 acc = *(const float2*)(g_h + (size_t)node * H + c0);

    int beg = g_rowptr[node];
    int end = g_rowptr[node + 1];
    int e = 0, s = 0, e2 = 0, s2 = 0;
    float eav = 0.f;
    float2 hv = make_float2(0.f, 0.f);
    if (beg < end) {
        e = g_eid[beg];
        s = g_ssort[beg];
        eav = ea[(size_t)e * ED + lane];
        hv = *(const float2*)(g_h + (size_t)s * H + c0);
        if (beg + 1 < end) { e2 = g_eid[beg + 1]; s2 = g_ssort[beg + 1]; }
    }
    for (int j = beg; j < end; j++) {
        float ecur = eav;
        float2 hcur = hv;
        // prefetch j+1 data, j+2 indices
        if (j + 1 < end) {
            eav = ea[(size_t)e2 * ED + lane];
            hv = *(const float2*)(g_h + (size_t)s2 * H + c0);
            if (j + 2 < end) { e2 = g_eid[j + 2]; s2 = g_ssort[j + 2]; }
        }
        float mx = bias.x, my = bias.y;
#pragma unroll
        for (int k = 0; k < ED; k++) {
            float a = __shfl_sync(0xffffffffu, ecur, k);
            mx = fmaf(a, wreg[k].x, mx);
            my = fmaf(a, wreg[k].y, my);
        }
        acc.x += fmaxf(mx + hcur.x, 0.f);
        acc.y += fmaxf(my + hcur.y, 0.f);
    }
    *(float2*)(g_z + (size_t)node * H + c0) = acc;
}

// ---------------- 128x128-tile GEMM: C = A @ W + b ----------------
// which==0: A=g_z -> C=g_t, relu, block0 zeroes BN stats
// which==1: A=g_t -> C=g_z2, no relu, fused BN sum/sumsq reduction
__global__ void __launch_bounds__(256) k_mlp(int which, const float* __restrict__ W,
                                             const float* __restrict__ bias) {
    const float* A = which ? g_t : g_z;
    float* C = which ? g_z2 : g_t;
    __shared__ float As[128 * 36];
    __shared__ float Ws[32 * 128];
    int tid = threadIdx.x;
    int tx = tid & 15;
    int ty = tid >> 4;
    int row0 = blockIdx.x * 128;

    if (which == 0 && blockIdx.x == 0 && tid < H) {
        g_colsum[tid] = 0.f;
        g_colsq[tid] = 0.f;
    }

    float acc[8][8];
#pragma unroll
    for (int j = 0; j < 8; j++)
#pragma unroll
        for (int c = 0; c < 8; c++) acc[j][c] = 0.f;

    for (int kt = 0; kt < 4; kt++) {
        for (int i = tid; i < 1024; i += 256) {
            int r = i >> 3, c4 = i & 7;
            int gr = row0 + r;
            float4 v = make_float4(0.f, 0.f, 0.f, 0.f);
            if (gr < NN) v = *(const float4*)(A + (size_t)gr * H + kt * 32 + c4 * 4);
            *(float4*)(As + r * 36 + c4 * 4) = v;
        }
        for (int i = tid; i < 1024; i += 256) {
            int k = i >> 5, c4 = i & 31;
            *(float4*)(Ws + k * H + c4 * 4) =
                *(const float4*)(W + (size_t)(kt * 32 + k) * H + c4 * 4);
        }
        __syncthreads();
#pragma unroll
        for (int k = 0; k < 32; k++) {
            float4 w0 = *(const float4*)(Ws + k * H + tx * 8);
            float4 w1 = *(const float4*)(Ws + k * H + tx * 8 + 4);
            float a[8];
#pragma unroll
            for (int j = 0; j < 8; j++) a[j] = As[(ty * 8 + j) * 36 + k];
#pragma unroll
            for (int j = 0; j < 8; j++) {
                acc[j][0] = fmaf(a[j], w0.x, acc[j][0]);
                acc[j][1] = fmaf(a[j], w0.y, acc[j][1]);
                acc[j][2] = fmaf(a[j], w0.z, acc[j][2]);
                acc[j][3] = fmaf(a[j], w0.w, acc[j][3]);
                acc[j][4] = fmaf(a[j], w1.x, acc[j][4]);
                acc[j][5] = fmaf(a[j], w1.y, acc[j][5]);
                acc[j][6] = fmaf(a[j], w1.z, acc[j][6]);
                acc[j][7] = fmaf(a[j], w1.w, acc[j][7]);
            }
        }
        __syncthreads();
    }

    float4 b0 = *(const float4*)(bias + tx * 8);
    float4 b1 = *(const float4*)(bias + tx * 8 + 4);

    if (which == 0) {
#pragma unroll
        for (int j = 0; j < 8; j++) {
            int gr = row0 + ty * 8 + j;
            if (gr < NN) {
                float4 o0, o1;
                o0.x = fmaxf(acc[j][0] + b0.x, 0.f);
                o0.y = fmaxf(acc[j][1] + b0.y, 0.f);
                o0.z = fmaxf(acc[j][2] + b0.z, 0.f);
                o0.w = fmaxf(acc[j][3] + b0.w, 0.f);
                o1.x = fmaxf(acc[j][4] + b1.x, 0.f);
                o1.y = fmaxf(acc[j][5] + b1.y, 0.f);
                o1.z = fmaxf(acc[j][6] + b1.z, 0.f);
                o1.w = fmaxf(acc[j][7] + b1.w, 0.f);
                *(float4*)(C + (size_t)gr * H + tx * 8) = o0;
                *(float4*)(C + (size_t)gr * H + tx * 8 + 4) = o1;
            }
        }
    } else {
        float psum[8], psq[8];
#pragma unroll
        for (int c = 0; c < 8; c++) { psum[c] = 0.f; psq[c] = 0.f; }
#pragma unroll
        for (int j = 0; j < 8; j++) {
            int gr = row0 + ty * 8 + j;
            if (gr < NN) {
                float o[8];
                o[0] = acc[j][0] + b0.x; o[1] = acc[j][1] + b0.y;
                o[2] = acc[j][2] + b0.z; o[3] = acc[j][3] + b0.w;
                o[4] = acc[j][4] + b1.x; o[5] = acc[j][5] + b1.y;
                o[6] = acc[j][6] + b1.z; o[7] = acc[j][7] + b1.w;
                *(float4*)(C + (size_t)gr * H + tx * 8) = *(float4*)&o[0];
                *(float4*)(C + (size_t)gr * H + tx * 8 + 4) = *(float4*)&o[4];
#pragma unroll
                for (int c = 0; c < 8; c++) {
                    psum[c] += o[c];
                    psq[c] = fmaf(o[c], o[c], psq[c]);
                }
            }
        }
        __syncthreads();  // done with As/Ws
        float* Ssum = As;        // 16 x 128
        float* Ssq = Ws;         // 16 x 128
#pragma unroll
        for (int c = 0; c < 8; c++) {
            Ssum[ty * H + tx * 8 + c] = psum[c];
            Ssq[ty * H + tx * 8 + c] = psq[c];
        }
        __syncthreads();
        if (tid < H) {
            float s = 0.f, q = 0.f;
#pragma unroll
            for (int r = 0; r < 16; r++) {
                s += Ssum[r * H + tid];
                q += Ssq[r * H + tid];
            }
            atomicAdd(&g_colsum[tid], s);
            atomicAdd(&g_colsq[tid], q);
        }
    }
}

// ---------------- BN finalize ----------------
__global__ void k_bnfin(const float* __restrict__ gamma,
                        const float* __restrict__ beta) {
    int c = threadIdx.x;
    float mu = g_colsum[c] * (1.f / NN);
    float var = g_colsq[c] * (1.f / NN) - mu * mu;
    float rs = rsqrtf(var + BN_EPS);
    float sc = rs * gamma[c];
    g_scale[c] = sc;
    g_shift[c] = beta[c] - mu * sc;
}

// ---------------- BN apply + relu + residual ----------------
__global__ void k_post(float* __restrict__ dout, int use_dout) {
    int i = blockIdx.x * blockDim.x + threadIdx.x;
    if (i >= NN * H / 4) return;
    int c4 = i & 31;
    float4 z = ((const float4*)g_z2)[i];
    float4 sc = ((const float4*)g_scale)[c4];
    float4 sh = ((const float4*)g_shift)[c4];
    float4 hr = ((const float4*)g_h)[i];
    float4 o;
    o.x = fmaxf(fmaf(z.x, sc.x, sh.x), 0.f) + RES_SCALE * hr.x;
    o.y = fmaxf(fmaf(z.y, sc.y, sh.y), 0.f) + RES_SCALE * hr.y;
    o.z = fmaxf(fmaf(z.z, sc.z, sh.z), 0.f) + RES_SCALE * hr.z;
    o.w = fmaxf(fmaf(z.w, sc.w, sh.w), 0.f) + RES_SCALE * hr.w;
    float4* out = use_dout ? (float4*)dout : (float4*)g_h;
    out[i] = o;
}

// ---------------- launch ----------------
extern "C" void kernel_launch(void* const* d_in, const int* in_sizes, int n_in,
                              void* d_out, int out_size) {
    const float* x = (const float*)d_in[0];
    const int* ei = (const int*)d_in[1];
    const float* ea = (const float*)d_in[2];
    const float* We = (const float*)d_in[3];
    const float* be = (const float*)d_in[4];
    const float* W1 = (const float*)d_in[5];
    const float* b1 = (const float*)d_in[6];
    const float* W2 = (const float*)d_in[7];
    const float* b2 = (const float*)d_in[8];
    const float* gamma = (const float*)d_in[9];
    const float* beta = (const float*)d_in[10];

    k_init<<<(NN * H + 255) / 256, 256>>>(x);
    k_detect<<<1, 32>>>(ei);
    k_prep<<<(NE + 255) / 256, 256>>>(ei);
    k_scan<<<1, 1024>>>();
    k_scatter<<<(NE + 255) / 256, 256>>>();

    for (int l = 0; l < 3; l++) {
        k_agg<<<(NN + 3) / 4, 256>>>(ea, We + (size_t)l * ED * H, be + (size_t)l * H);
        k_mlp<<<(NN + 127) / 128, 256>>>(0, W1 + (size_t)l * H * H, b1 + (size_t)l * H);
        k_mlp<<<(NN + 127) / 128, 256>>>(1, W2 + (size_t)l * H * H, b2 + (size_t)l * H);
        k_bnfin<<<1, 128>>>(gamma + (size_t)l * H, beta + (size_t)l * H);
        k_post<<<(NN * H / 4 + 255) / 256, 256>>>((float*)d_out, l == 2 ? 1 : 0);
    }
}